// round 16
// baseline (speedup 1.0000x reference)
#include <cuda_runtime.h>
#include <cuda_fp16.h>
#include <cstdint>

// Problem constants
#define PB  8
#define PS  1024
#define PH  768
#define PNH 12
#define PDH 64
#define PM  (PB * PS)          // 8192
#define PELEMS (PM * PH)       // 6291456
#define WN  (PH * PH)          // 589824
#define LQKV 2304              // fused q|k|v row stride

// ---------------------------------------------------------------------------
// Scratch (static device globals — no allocation)
// ---------------------------------------------------------------------------
__device__ __half g_xh [PELEMS];
__device__ __half g_yh [PELEMS];
__device__ __half g_qkvx[PM * LQKV];
__device__ __half g_qkvy[PM * LQKV];
__device__ __half g_cxh[PELEMS];
__device__ __half g_cyh[PELEMS];
__device__ __half g_w[8 * WN];
__device__ float g_bcx[LQKV], g_bcy[LQKV];

// ---------------------------------------------------------------------------
// Helpers (sm_80+-portable: ldmatrix + mma.sync + cp.async only)
// ---------------------------------------------------------------------------
__device__ __forceinline__ uint32_t smem_u32(const void* p) {
    uint32_t a;
    asm("{ .reg .u64 t; cvta.to.shared.u64 t, %1; cvt.u32.u64 %0, t; }"
        : "=r"(a) : "l"(p));
    return a;
}

__device__ __forceinline__ void cpasync16(uint32_t dst, const void* src) {
    asm volatile("cp.async.cg.shared.global [%0], [%1], 16;"
                 :: "r"(dst), "l"(src));
}
#define CP_COMMIT() asm volatile("cp.async.commit_group;")
#define CP_WAIT(n)  asm volatile("cp.async.wait_group %0;" :: "n"(n))

__device__ __forceinline__ void ldm4(uint32_t r[4], uint32_t addr) {
    asm volatile("ldmatrix.sync.aligned.m8n8.x4.shared.b16 {%0,%1,%2,%3}, [%4];"
        : "=r"(r[0]), "=r"(r[1]), "=r"(r[2]), "=r"(r[3]) : "r"(addr));
}
__device__ __forceinline__ void ldm4t(uint32_t r[4], uint32_t addr) {
    asm volatile("ldmatrix.sync.aligned.m8n8.x4.trans.shared.b16 {%0,%1,%2,%3}, [%4];"
        : "=r"(r[0]), "=r"(r[1]), "=r"(r[2]), "=r"(r[3]) : "r"(addr));
}

__device__ __forceinline__ void mma16816(float c[4], const uint32_t a[4],
                                         const uint32_t b[2]) {
    asm volatile("mma.sync.aligned.m16n8k16.row.col.f32.f16.f16.f32 "
        "{%0,%1,%2,%3}, {%4,%5,%6,%7}, {%8,%9}, {%0,%1,%2,%3};"
        : "+f"(c[0]), "+f"(c[1]), "+f"(c[2]), "+f"(c[3])
        : "r"(a[0]), "r"(a[1]), "r"(a[2]), "r"(a[3]), "r"(b[0]), "r"(b[1]));
}

__device__ __forceinline__ uint32_t packh(__half a, __half b) {
    __half2 t = __halves2half2(a, b);
    return *(uint32_t*)&t;
}

__device__ __forceinline__ float ex2(float x) {
    float r;
    asm("ex2.approx.f32 %0, %1;" : "=f"(r) : "f"(x));
    return r;
}

// ---------------------------------------------------------------------------
// fp32 -> fp16 conversions ; bias concatenation
// ---------------------------------------------------------------------------
__global__ void cvt_inputs(const float* __restrict__ hx, const float* __restrict__ hy,
                           __half* __restrict__ xh, __half* __restrict__ yh)
{
    int i = blockIdx.x * blockDim.x + threadIdx.x;
    if (i >= PELEMS / 4) return;
    const float* src = blockIdx.y ? hy : hx;
    __half* dst = blockIdx.y ? yh : xh;
    float4 v = *(const float4*)(src + (size_t)i * 4);
    ((__half2*)dst)[i * 2 + 0] = __halves2half2(__float2half_rn(v.x), __float2half_rn(v.y));
    ((__half2*)dst)[i * 2 + 1] = __halves2half2(__float2half_rn(v.z), __float2half_rn(v.w));
}

__global__ void cvt_weights(const float* w0, const float* w1, const float* w2,
                            const float* w3, const float* w4, const float* w5,
                            const float* w6, const float* w7,
                            __half* __restrict__ dst)
{
    int i = blockIdx.x * blockDim.x + threadIdx.x;
    if (i >= WN / 4) return;
    const int s = blockIdx.y;
    const float* src;
    switch (s) {
        case 0: src = w0; break; case 1: src = w1; break;
        case 2: src = w2; break; case 3: src = w3; break;
        case 4: src = w4; break; case 5: src = w5; break;
        case 6: src = w6; break; default: src = w7; break;
    }
    float4 v = *(const float4*)(src + (size_t)i * 4);
    __half2* ph = (__half2*)(dst + (size_t)s * WN);
    ph[i * 2 + 0] = __halves2half2(__float2half_rn(v.x), __float2half_rn(v.y));
    ph[i * 2 + 1] = __halves2half2(__float2half_rn(v.z), __float2half_rn(v.w));
}

__global__ void concat_biases(const float* __restrict__ a0, const float* __restrict__ a1,
                              const float* __restrict__ a2, float* __restrict__ ox,
                              const float* __restrict__ b0, const float* __restrict__ b1,
                              const float* __restrict__ b2, float* __restrict__ oy)
{
    int i = blockIdx.x * blockDim.x + threadIdx.x;
    const float* s0 = blockIdx.y ? b0 : a0;
    const float* s1 = blockIdx.y ? b1 : a1;
    const float* s2 = blockIdx.y ? b2 : a2;
    float* o = blockIdx.y ? oy : ox;
    if (i < PH) o[i] = s0[i];
    else if (i < 2 * PH) o[i] = s1[i - PH];
    else if (i < 3 * PH) o[i] = s2[i - 2 * PH];
}

// ---------------------------------------------------------------------------
// fp16 GEMM: C[M,N] = A[M,768] @ W[N,768]^T + bscale*bias
// Single fp16 planes. CTA tile 128x128, K-chunk 32, cp.async 3-stage
// pipeline, ONE barrier per iteration. 256 threads. Dual-config dispatch.
// ---------------------------------------------------------------------------
#define GBK   32
#define GKCH  (PH / GBK)         // 24
#define GSA   40                 // smem row stride fp16 (80B)
#define PLANE_B (128 * GSA * 2)  // 10240
#define STAGE_B (2 * PLANE_B)    // 20480  [A][W]
#define GEMM_SMEM (3 * STAGE_B)  // 61440

__global__ void __launch_bounds__(256)
mm_gemm(const __half* __restrict__ A1, const __half* __restrict__ W1,
        const float* __restrict__ bias1,
        const float* __restrict__ s1a, const float* __restrict__ s1b,
        float* __restrict__ Cf1, __half* __restrict__ C1h,
        const __half* __restrict__ A2, const __half* __restrict__ W2,
        const float* __restrict__ bias2,
        const float* __restrict__ s2a, const float* __restrict__ s2b,
        float* __restrict__ Cf2, __half* __restrict__ C2h,
        int lda, int ldc)
{
    extern __shared__ char smem[];
    const uint32_t sb = smem_u32(smem);
    const int tid = threadIdx.x;
    const int wid = tid >> 5, lane = tid & 31;
    const int warpM = wid >> 2, warpN = wid & 3;

    int by = blockIdx.y;
    const bool second = (by >= 64);
    if (second) by -= 64;

    const __half* A        = second ? A2    : A1;
    const __half* W        = second ? W2    : W1;
    const float* bias      = second ? bias2 : bias1;
    const float* sa        = second ? s2a   : s1a;
    const float* sbv       = second ? s2b   : s1b;
    float* Cf              = second ? Cf2   : Cf1;
    __half* Ch             = second ? C2h   : C1h;

    const int row0 = by * 128, col0 = blockIdx.x * 128;

    const __half* g0 = A + (size_t)row0 * lda;
    const __half* g2 = W + (size_t)col0 * PH;

    float acc[4][4][4];
    #pragma unroll
    for (int mt = 0; mt < 4; mt++)
        #pragma unroll
        for (int nt = 0; nt < 4; nt++)
            #pragma unroll
            for (int c = 0; c < 4; c++) acc[mt][nt][c] = 0.0f;

    const int arow  = warpM * 64 + (lane & 15);
    const int akh   = lane >> 4;
    const int bkey  = warpN * 32 + (lane & 7) + ((lane >> 4) << 3);
    const int bkh   = (lane >> 3) & 1;

#define G_LOAD(kc, st) do {                                                   \
    const uint32_t dbase = sb + (st) * STAGE_B;                               \
    _Pragma("unroll")                                                         \
    for (int j = 0; j < 2; j++) {                                             \
        const int cc = j * 256 + tid;                                         \
        const int r = cc >> 2, seg = cc & 3;                                  \
        const uint32_t so = r * (GSA * 2) + seg * 16;                         \
        const size_t goA = (size_t)r * lda + (kc) * GBK + seg * 8;            \
        const size_t goW = (size_t)r * PH  + (kc) * GBK + seg * 8;            \
        cpasync16(dbase + 0 * PLANE_B + so, g0 + goA);                        \
        cpasync16(dbase + 1 * PLANE_B + so, g2 + goW);                        \
    }                                                                         \
} while (0)

    G_LOAD(0, 0);
    CP_COMMIT();
    G_LOAD(1, 1);
    CP_COMMIT();

    for (int kc = 0; kc < GKCH; kc++) {
        if (kc + 1 < GKCH) { CP_WAIT(1); } else { CP_WAIT(0); }
        __syncthreads();
        if (kc + 2 < GKCH) {
            G_LOAD(kc + 2, (kc + 2) % 3);
            CP_COMMIT();
        }

        const uint32_t stb = sb + (kc % 3) * STAGE_B;
        #pragma unroll
        for (int ks = 0; ks < 2; ks++) {
            uint32_t af[4][4];
            #pragma unroll
            for (int mt = 0; mt < 4; mt++)
                ldm4(af[mt], stb + (arow + mt * 16) * (GSA * 2) + ks * 32 + akh * 16);
            uint32_t bf[4][2];
            #pragma unroll
            for (int ntp = 0; ntp < 2; ntp++) {
                const uint32_t addr = stb + PLANE_B
                                      + (bkey + ntp * 16) * (GSA * 2)
                                      + ks * 32 + bkh * 16;
                uint32_t t[4];
                ldm4(t, addr);
                bf[2 * ntp][0] = t[0]; bf[2 * ntp][1] = t[1];
                bf[2 * ntp + 1][0] = t[2]; bf[2 * ntp + 1][1] = t[3];
            }
            #pragma unroll
            for (int mt = 0; mt < 4; mt++)
                #pragma unroll
                for (int nt = 0; nt < 4; nt++)
                    mma16816(acc[mt][nt], af[mt], bf[nt]);
        }
    }

    const int g = lane >> 2, tig = lane & 3;
    const float bscale = sa ? (*sa + *sbv) : 1.0f;
    #pragma unroll
    for (int mt = 0; mt < 4; mt++) {
        const int r0 = row0 + warpM * 64 + mt * 16 + g;
        #pragma unroll
        for (int nt = 0; nt < 4; nt++) {
            const int col = col0 + warpN * 32 + nt * 8 + tig * 2;
            const float b0 = bscale * bias[col];
            const float b1 = bscale * bias[col + 1];
            const float v00 = acc[mt][nt][0] + b0, v01 = acc[mt][nt][1] + b1;
            const float v10 = acc[mt][nt][2] + b0, v11 = acc[mt][nt][3] + b1;
            if (Cf) {
                *(float2*)(Cf + (size_t)r0 * ldc + col)       = make_float2(v00, v01);
                *(float2*)(Cf + (size_t)(r0 + 8) * ldc + col) = make_float2(v10, v11);
            }
            if (Ch) {
                *(__half2*)(Ch + (size_t)r0 * ldc + col) =
                    __halves2half2(__float2half_rn(v00), __float2half_rn(v01));
                *(__half2*)(Ch + (size_t)(r0 + 8) * ldc + col) =
                    __halves2half2(__float2half_rn(v10), __float2half_rn(v11));
            }
        }
    }
}

// ---------------------------------------------------------------------------
// Dual-stream flash attention, fp16 single-plane Q/K/V, both outputs in one
// launch. 128 q-rows per CTA, 8 warps (256 thr), double-buffered KV tiles,
// one barrier per tile, base-2 softmax with raw ex2.approx.
// blockIdx.x&1 selects output stream; adjacent CTAs share KV tiles in L2.
// smem: [Q(18432)][K0][V0][K1][V1]  (9216 each) = 55296
// ---------------------------------------------------------------------------
#define AST     72                    // fp16 row stride (144B)
#define ROWB    (AST * 2)             // 144
#define AQ_B    (128 * ROWB)          // 18432
#define ATILE_B (64 * ROWB)           // 9216
#define ATT_SMEM (AQ_B + 4 * ATILE_B) // 55296
#define SC2     0.1803368801f         // 0.125 * log2(e)

__global__ void __launch_bounds__(256)
attn_mma(const __half* __restrict__ qkvx, const __half* __restrict__ qkvy,
         const float* __restrict__ pw11, const float* __restrict__ pw12,
         const float* __restrict__ pw21, const float* __restrict__ pw22,
         __half* __restrict__ cxh, __half* __restrict__ cyh)
{
    extern __shared__ char smem[];
    const uint32_t sb = smem_u32(smem);

    const int st = blockIdx.x & 1;
    const int qt = blockIdx.x >> 1;
    const int h = blockIdx.y, b = blockIdx.z;
    const int tid = threadIdx.x, wid = tid >> 5, lane = tid & 31;
    const int g = lane >> 2, tig = lane & 3;

    const __half* Qh = st ? qkvy : qkvx;
    const __half* const KH[2] = { qkvx + PH, qkvy + PH };
    const __half* const VH[2] = { qkvx + 2 * PH, qkvy + 2 * PH };
    const float ws0 = st ? *pw22 : *pw11;
    const float ws1 = st ? *pw21 : *pw12;
    __half* ctx = st ? cyh : cxh;

    // --- load Q tile (128 rows) via cp.async ---
    #pragma unroll
    for (int j = 0; j < 4; j++) {
        const int cc = j * 256 + tid;        // 1024 chunks
        const int r = cc >> 3, seg = cc & 7;
        const size_t go = (size_t)(b * PS + qt * 128 + r) * LQKV + h * PDH + seg * 8;
        cpasync16(sb + r * ROWB + seg * 16, Qh + go);
    }
    CP_COMMIT();
    CP_WAIT(0);
    __syncthreads();

    // --- Q fragments (registers, reused across phases) ---
    uint32_t qf[4][4];
    {
        const int qrow = wid * 16 + (lane & 15);
        const int khalf = lane >> 4;
        #pragma unroll
        for (int ks = 0; ks < 4; ks++)
            ldm4(qf[ks], sb + qrow * ROWB + ks * 32 + khalf * 16);
    }

    const int bkey = (lane & 7) + ((lane >> 4) << 3);
    const int bkh  = (lane >> 3) & 1;
    const int vkey = (lane & 7) + (((lane >> 3) & 1) << 3);
    const int vdh  = (lane >> 4) << 3;

#define KV_LOAD(Kp, Vp, kt, buf) do {                                         \
    const uint32_t kbase = sb + AQ_B + (buf) * 2 * ATILE_B;                   \
    _Pragma("unroll")                                                         \
    for (int j = 0; j < 2; j++) {                                             \
        const int cc = j * 256 + tid;                                         \
        const int r = cc >> 3, seg = cc & 7;                                  \
        const size_t go = (size_t)(b * PS + (kt) * 64 + r) * LQKV             \
                          + h * PDH + seg * 8;                                \
        const uint32_t so = r * ROWB + seg * 16;                              \
        cpasync16(kbase + so,           Kp + go);                             \
        cpasync16(kbase + ATILE_B + so, Vp + go);                             \
    }                                                                         \
    CP_COMMIT();                                                              \
} while (0)

    float ostash[8][4];

    for (int s = 0; s < 2; s++) {
        const __half* Kh_ = KH[s];
        const __half* Vh_ = VH[s];

        float m[2] = { -1e30f, -1e30f }, l[2] = { 0.0f, 0.0f };
        float oacc[8][4];
        #pragma unroll
        for (int nt = 0; nt < 8; nt++)
            #pragma unroll
            for (int c = 0; c < 4; c++) oacc[nt][c] = 0.0f;

        KV_LOAD(Kh_, Vh_, 0, 0);

        for (int kt = 0; kt < PS / 64; kt++) {
            CP_WAIT(0);          // tile kt resident (this thread's parts)
            __syncthreads();     // all parts visible; compute kt-1 done
            if (kt + 1 < PS / 64)
                KV_LOAD(Kh_, Vh_, kt + 1, (kt + 1) & 1);

            const uint32_t kh_s = sb + AQ_B + (kt & 1) * 2 * ATILE_B;
            const uint32_t vh_s = kh_s + ATILE_B;

            // --- scores S = Q @ K^T ---
            float sacc[8][4];
            #pragma unroll
            for (int nt = 0; nt < 8; nt++)
                #pragma unroll
                for (int c = 0; c < 4; c++) sacc[nt][c] = 0.0f;

            #pragma unroll
            for (int ks = 0; ks < 4; ks++) {
                #pragma unroll
                for (int ntp = 0; ntp < 4; ntp++) {
                    const uint32_t addr = kh_s + (ntp * 16 + bkey) * ROWB
                                          + ks * 32 + bkh * 16;
                    uint32_t th[4];
                    ldm4(th, addr);
                    const uint32_t b0h[2] = { th[0], th[1] }, b1h[2] = { th[2], th[3] };
                    mma16816(sacc[2 * ntp],     qf[ks], b0h);
                    mma16816(sacc[2 * ntp + 1], qf[ks], b1h);
                }
            }

            // --- online softmax in base-2 (raw ex2.approx) ---
            #pragma unroll
            for (int nt = 0; nt < 8; nt++)
                #pragma unroll
                for (int c = 0; c < 4; c++) sacc[nt][c] *= SC2;

            #pragma unroll
            for (int half = 0; half < 2; half++) {
                float mx = -1e30f;
                #pragma unroll
                for (int nt = 0; nt < 8; nt++)
                    mx = fmaxf(mx, fmaxf(sacc[nt][2 * half], sacc[nt][2 * half + 1]));
                mx = fmaxf(mx, __shfl_xor_sync(0xffffffffu, mx, 1));
                mx = fmaxf(mx, __shfl_xor_sync(0xffffffffu, mx, 2));
                const float mn = fmaxf(m[half], mx);
                const float corr = ex2(m[half] - mn);
                m[half] = mn;
                float rs = 0.0f;
                #pragma unroll
                for (int nt = 0; nt < 8; nt++) {
                    const float p0 = ex2(sacc[nt][2 * half] - mn);
                    const float p1 = ex2(sacc[nt][2 * half + 1] - mn);
                    sacc[nt][2 * half] = p0;
                    sacc[nt][2 * half + 1] = p1;
                    rs += p0 + p1;
                }
                rs += __shfl_xor_sync(0xffffffffu, rs, 1);
                rs += __shfl_xor_sync(0xffffffffu, rs, 2);
                l[half] = l[half] * corr + rs;
                #pragma unroll
                for (int nt = 0; nt < 8; nt++) {
                    oacc[nt][2 * half]     *= corr;
                    oacc[nt][2 * half + 1] *= corr;
                }
            }

            // --- pack P into fp16 A-fragments ---
            uint32_t ph[8][2];
            #pragma unroll
            for (int nt = 0; nt < 8; nt++) {
                #pragma unroll
                for (int half = 0; half < 2; half++) {
                    ph[nt][half] = packh(__float2half_rn(sacc[nt][2 * half]),
                                         __float2half_rn(sacc[nt][2 * half + 1]));
                }
            }

            // --- O += P @ V ---
            #pragma unroll
            for (int ks = 0; ks < 4; ks++) {
                const uint32_t pa[4] = { ph[2 * ks][0], ph[2 * ks][1],
                                         ph[2 * ks + 1][0], ph[2 * ks + 1][1] };
                #pragma unroll
                for (int dhp = 0; dhp < 4; dhp++) {
                    const uint32_t addr = vh_s + (ks * 16 + vkey) * ROWB
                                          + (dhp * 16 + vdh) * 2;
                    uint32_t th[4];
                    ldm4t(th, addr);
                    const uint32_t b0h[2] = { th[0], th[1] }, b1h[2] = { th[2], th[3] };
                    mma16816(oacc[2 * dhp],     pa, b0h);
                    mma16816(oacc[2 * dhp + 1], pa, b1h);
                }
            }
        }

        if (s == 0) {
            const float i0 = ws0 / l[0], i1 = ws0 / l[1];
            #pragma unroll
            for (int nt = 0; nt < 8; nt++) {
                ostash[nt][0] = oacc[nt][0] * i0;
                ostash[nt][1] = oacc[nt][1] * i0;
                ostash[nt][2] = oacc[nt][2] * i1;
                ostash[nt][3] = oacc[nt][3] * i1;
            }
        } else {
            const float i0 = ws1 / l[0], i1 = ws1 / l[1];
            const int r0 = qt * 128 + wid * 16 + g;
            #pragma unroll
            for (int nt = 0; nt < 8; nt++) {
                const int col = h * PDH + nt * 8 + tig * 2;
                const float v00 = ostash[nt][0] + oacc[nt][0] * i0;
                const float v01 = ostash[nt][1] + oacc[nt][1] * i0;
                const float v10 = ostash[nt][2] + oacc[nt][2] * i1;
                const float v11 = ostash[nt][3] + oacc[nt][3] * i1;
                const size_t o0 = (size_t)(b * PS + r0) * PH + col;
                const size_t o1 = (size_t)(b * PS + r0 + 8) * PH + col;
                *(__half2*)(ctx + o0) = __halves2half2(__float2half_rn(v00),
                                                       __float2half_rn(v01));
                *(__half2*)(ctx + o1) = __halves2half2(__float2half_rn(v10),
                                                       __float2half_rn(v11));
            }
        }
    }
}

// ---------------------------------------------------------------------------
// Launch
// ---------------------------------------------------------------------------
extern "C" void kernel_launch(void* const* d_in, const int* in_sizes, int n_in,
                              void* d_out, int out_size)
{
    const float* hx = (const float*)d_in[0];
    const float* hy = (const float*)d_in[1];
    const float* Wf[8] = { (const float*)d_in[2],  (const float*)d_in[4],
                           (const float*)d_in[6],  (const float*)d_in[8],
                           (const float*)d_in[10], (const float*)d_in[12],
                           (const float*)d_in[14], (const float*)d_in[16] };
    const float* Bf[8] = { (const float*)d_in[3],  (const float*)d_in[5],
                           (const float*)d_in[7],  (const float*)d_in[9],
                           (const float*)d_in[11], (const float*)d_in[13],
                           (const float*)d_in[15], (const float*)d_in[17] };
    // order: 0=q 1=k 2=v 3=o 4=qd 5=kd 6=vd 7=od
    const float* pw11 = (const float*)d_in[18];
    const float* pw12 = (const float*)d_in[19];
    const float* pw21 = (const float*)d_in[20];
    const float* pw22 = (const float*)d_in[21];
    float* out = (float*)d_out;

    __half *xh, *yh, *qkvx, *qkvy, *cxh, *cyh, *w;
    float *bcx, *bcy;
    cudaGetSymbolAddress((void**)&xh,   g_xh);
    cudaGetSymbolAddress((void**)&yh,   g_yh);
    cudaGetSymbolAddress((void**)&qkvx, g_qkvx);
    cudaGetSymbolAddress((void**)&qkvy, g_qkvy);
    cudaGetSymbolAddress((void**)&cxh,  g_cxh);
    cudaGetSymbolAddress((void**)&cyh,  g_cyh);
    cudaGetSymbolAddress((void**)&w,    g_w);
    cudaGetSymbolAddress((void**)&bcx,  g_bcx);
    cudaGetSymbolAddress((void**)&bcy,  g_bcy);

    // conversions + bias concat
    {
        const int n4a = PELEMS / 4, n4w = WN / 4;
        dim3 gi((n4a + 255) / 256, 2);
        cvt_inputs<<<gi, 256>>>(hx, hy, xh, yh);
        dim3 gw((n4w + 255) / 256, 8);
        cvt_weights<<<gw, 256>>>(Wf[0], Wf[1], Wf[2], Wf[3],
                                 Wf[4], Wf[5], Wf[6], Wf[7], w);
        concat_biases<<<dim3(9, 2), 256>>>(Bf[0], Bf[1], Bf[2], bcx,
                                           Bf[4], Bf[5], Bf[6], bcy);
    }

    cudaFuncSetAttribute(mm_gemm, cudaFuncAttributeMaxDynamicSharedMemorySize,
                         GEMM_SMEM);
    cudaFuncSetAttribute(attn_mma, cudaFuncAttributeMaxDynamicSharedMemorySize,
                         ATT_SMEM);

    // fused QKV projections for BOTH streams in one launch (N = 2304)
    {
        const dim3 gq(LQKV / 128, 2 * (PM / 128));    // (18, 128)
        mm_gemm<<<gq, 256, GEMM_SMEM>>>(
            xh, w + 0 * (size_t)WN, bcx, nullptr, nullptr, nullptr, qkvx,
            yh, w + 4 * (size_t)WN, bcy, nullptr, nullptr, nullptr, qkvy,
            PH, LQKV);
    }

    // dual-stream flash attention, both outputs in one launch
    {
        const dim3 ga(2 * (PS / 128), PNH, PB);       // (16, 12, 8)
        attn_mma<<<ga, 256, ATT_SMEM>>>(qkvx, qkvy,
                                        pw11, pw12, pw21, pw22, cxh, cyh);
    }

    // output projections for BOTH streams in one launch
    {
        const dim3 go(PH / 128, 2 * (PM / 128));      // (6, 128)
        mm_gemm<<<go, 256, GEMM_SMEM>>>(
            cxh, w + 3 * (size_t)WN, Bf[3], pw11, pw12, out, nullptr,
            cyh, w + 7 * (size_t)WN, Bf[7], pw21, pw22, out + (size_t)PM * PH, nullptr,
            PH, PH);
    }
}

// round 17
// speedup vs baseline: 1.1353x; 1.1353x over previous
#include <cuda_runtime.h>
#include <cuda_fp16.h>
#include <cstdint>

// Problem constants
#define PB  8
#define PS  1024
#define PH  768
#define PNH 12
#define PDH 64
#define PM  (PB * PS)          // 8192
#define PELEMS (PM * PH)       // 6291456
#define WN  (PH * PH)          // 589824
#define LQKV 2304              // fused q|k|v row stride

// ---------------------------------------------------------------------------
// Scratch (static device globals — no allocation)
// ---------------------------------------------------------------------------
__device__ __half g_xh [PELEMS];
__device__ __half g_yh [PELEMS];
__device__ __half g_qkvx[PM * LQKV];
__device__ __half g_qkvy[PM * LQKV];
__device__ __half g_cxh[PELEMS];
__device__ __half g_cyh[PELEMS];
__device__ __half g_w[8 * WN];
__device__ float g_bcx[LQKV], g_bcy[LQKV];

// ---------------------------------------------------------------------------
// Helpers (sm_80+-portable: ldmatrix + mma.sync + cp.async only)
// ---------------------------------------------------------------------------
__device__ __forceinline__ uint32_t smem_u32(const void* p) {
    uint32_t a;
    asm("{ .reg .u64 t; cvta.to.shared.u64 t, %1; cvt.u32.u64 %0, t; }"
        : "=r"(a) : "l"(p));
    return a;
}

__device__ __forceinline__ void cpasync16(uint32_t dst, const void* src) {
    asm volatile("cp.async.cg.shared.global [%0], [%1], 16;"
                 :: "r"(dst), "l"(src));
}
#define CP_COMMIT() asm volatile("cp.async.commit_group;")
#define CP_WAIT(n)  asm volatile("cp.async.wait_group %0;" :: "n"(n))

__device__ __forceinline__ void ldm4(uint32_t r[4], uint32_t addr) {
    asm volatile("ldmatrix.sync.aligned.m8n8.x4.shared.b16 {%0,%1,%2,%3}, [%4];"
        : "=r"(r[0]), "=r"(r[1]), "=r"(r[2]), "=r"(r[3]) : "r"(addr));
}
__device__ __forceinline__ void ldm4t(uint32_t r[4], uint32_t addr) {
    asm volatile("ldmatrix.sync.aligned.m8n8.x4.trans.shared.b16 {%0,%1,%2,%3}, [%4];"
        : "=r"(r[0]), "=r"(r[1]), "=r"(r[2]), "=r"(r[3]) : "r"(addr));
}

__device__ __forceinline__ void mma16816(float c[4], const uint32_t a[4],
                                         const uint32_t b[2]) {
    asm volatile("mma.sync.aligned.m16n8k16.row.col.f32.f16.f16.f32 "
        "{%0,%1,%2,%3}, {%4,%5,%6,%7}, {%8,%9}, {%0,%1,%2,%3};"
        : "+f"(c[0]), "+f"(c[1]), "+f"(c[2]), "+f"(c[3])
        : "r"(a[0]), "r"(a[1]), "r"(a[2]), "r"(a[3]), "r"(b[0]), "r"(b[1]));
}

__device__ __forceinline__ uint32_t packh(__half a, __half b) {
    __half2 t = __halves2half2(a, b);
    return *(uint32_t*)&t;
}

__device__ __forceinline__ float ex2(float x) {
    float r;
    asm("ex2.approx.f32 %0, %1;" : "=f"(r) : "f"(x));
    return r;
}

// ---------------------------------------------------------------------------
// fp32 -> fp16 conversions ; bias concatenation
// ---------------------------------------------------------------------------
__global__ void cvt_inputs(const float* __restrict__ hx, const float* __restrict__ hy,
                           __half* __restrict__ xh, __half* __restrict__ yh)
{
    int i = blockIdx.x * blockDim.x + threadIdx.x;
    if (i >= PELEMS / 4) return;
    const float* src = blockIdx.y ? hy : hx;
    __half* dst = blockIdx.y ? yh : xh;
    float4 v = *(const float4*)(src + (size_t)i * 4);
    ((__half2*)dst)[i * 2 + 0] = __halves2half2(__float2half_rn(v.x), __float2half_rn(v.y));
    ((__half2*)dst)[i * 2 + 1] = __halves2half2(__float2half_rn(v.z), __float2half_rn(v.w));
}

__global__ void cvt_weights(const float* w0, const float* w1, const float* w2,
                            const float* w3, const float* w4, const float* w5,
                            const float* w6, const float* w7,
                            __half* __restrict__ dst)
{
    int i = blockIdx.x * blockDim.x + threadIdx.x;
    if (i >= WN / 4) return;
    const int s = blockIdx.y;
    const float* src;
    switch (s) {
        case 0: src = w0; break; case 1: src = w1; break;
        case 2: src = w2; break; case 3: src = w3; break;
        case 4: src = w4; break; case 5: src = w5; break;
        case 6: src = w6; break; default: src = w7; break;
    }
    float4 v = *(const float4*)(src + (size_t)i * 4);
    __half2* ph = (__half2*)(dst + (size_t)s * WN);
    ph[i * 2 + 0] = __halves2half2(__float2half_rn(v.x), __float2half_rn(v.y));
    ph[i * 2 + 1] = __halves2half2(__float2half_rn(v.z), __float2half_rn(v.w));
}

__global__ void concat_biases(const float* __restrict__ a0, const float* __restrict__ a1,
                              const float* __restrict__ a2, float* __restrict__ ox,
                              const float* __restrict__ b0, const float* __restrict__ b1,
                              const float* __restrict__ b2, float* __restrict__ oy)
{
    int i = blockIdx.x * blockDim.x + threadIdx.x;
    const float* s0 = blockIdx.y ? b0 : a0;
    const float* s1 = blockIdx.y ? b1 : a1;
    const float* s2 = blockIdx.y ? b2 : a2;
    float* o = blockIdx.y ? oy : ox;
    if (i < PH) o[i] = s0[i];
    else if (i < 2 * PH) o[i] = s1[i - PH];
    else if (i < 3 * PH) o[i] = s2[i - 2 * PH];
}

// ---------------------------------------------------------------------------
// fp16 GEMM: C[M,N] = A[M,768] @ W[N,768]^T + bscale*bias
// Single fp16 planes. CTA tile 128x128, K-chunk 32, cp.async 3-stage
// pipeline, ONE barrier per iteration. 256 threads. Dual-config dispatch.
// ---------------------------------------------------------------------------
#define GBK   32
#define GKCH  (PH / GBK)         // 24
#define GSA   40                 // smem row stride fp16 (80B)
#define PLANE_B (128 * GSA * 2)  // 10240
#define STAGE_B (2 * PLANE_B)    // 20480  [A][W]
#define GEMM_SMEM (3 * STAGE_B)  // 61440

__global__ void __launch_bounds__(256)
mm_gemm(const __half* __restrict__ A1, const __half* __restrict__ W1,
        const float* __restrict__ bias1,
        const float* __restrict__ s1a, const float* __restrict__ s1b,
        float* __restrict__ Cf1, __half* __restrict__ C1h,
        const __half* __restrict__ A2, const __half* __restrict__ W2,
        const float* __restrict__ bias2,
        const float* __restrict__ s2a, const float* __restrict__ s2b,
        float* __restrict__ Cf2, __half* __restrict__ C2h,
        int lda, int ldc)
{
    extern __shared__ char smem[];
    const uint32_t sb = smem_u32(smem);
    const int tid = threadIdx.x;
    const int wid = tid >> 5, lane = tid & 31;
    const int warpM = wid >> 2, warpN = wid & 3;

    int by = blockIdx.y;
    const bool second = (by >= 64);
    if (second) by -= 64;

    const __half* A        = second ? A2    : A1;
    const __half* W        = second ? W2    : W1;
    const float* bias      = second ? bias2 : bias1;
    const float* sa        = second ? s2a   : s1a;
    const float* sbv       = second ? s2b   : s1b;
    float* Cf              = second ? Cf2   : Cf1;
    __half* Ch             = second ? C2h   : C1h;

    const int row0 = by * 128, col0 = blockIdx.x * 128;

    const __half* g0 = A + (size_t)row0 * lda;
    const __half* g2 = W + (size_t)col0 * PH;

    float acc[4][4][4];
    #pragma unroll
    for (int mt = 0; mt < 4; mt++)
        #pragma unroll
        for (int nt = 0; nt < 4; nt++)
            #pragma unroll
            for (int c = 0; c < 4; c++) acc[mt][nt][c] = 0.0f;

    const int arow  = warpM * 64 + (lane & 15);
    const int akh   = lane >> 4;
    const int bkey  = warpN * 32 + (lane & 7) + ((lane >> 4) << 3);
    const int bkh   = (lane >> 3) & 1;

#define G_LOAD(kc, st) do {                                                   \
    const uint32_t dbase = sb + (st) * STAGE_B;                               \
    _Pragma("unroll")                                                         \
    for (int j = 0; j < 2; j++) {                                             \
        const int cc = j * 256 + tid;                                         \
        const int r = cc >> 2, seg = cc & 3;                                  \
        const uint32_t so = r * (GSA * 2) + seg * 16;                         \
        const size_t goA = (size_t)r * lda + (kc) * GBK + seg * 8;            \
        const size_t goW = (size_t)r * PH  + (kc) * GBK + seg * 8;            \
        cpasync16(dbase + 0 * PLANE_B + so, g0 + goA);                        \
        cpasync16(dbase + 1 * PLANE_B + so, g2 + goW);                        \
    }                                                                         \
} while (0)

    G_LOAD(0, 0);
    CP_COMMIT();
    G_LOAD(1, 1);
    CP_COMMIT();

    for (int kc = 0; kc < GKCH; kc++) {
        if (kc + 1 < GKCH) { CP_WAIT(1); } else { CP_WAIT(0); }
        __syncthreads();
        if (kc + 2 < GKCH) {
            G_LOAD(kc + 2, (kc + 2) % 3);
            CP_COMMIT();
        }

        const uint32_t stb = sb + (kc % 3) * STAGE_B;
        #pragma unroll
        for (int ks = 0; ks < 2; ks++) {
            uint32_t af[4][4];
            #pragma unroll
            for (int mt = 0; mt < 4; mt++)
                ldm4(af[mt], stb + (arow + mt * 16) * (GSA * 2) + ks * 32 + akh * 16);
            uint32_t bf[4][2];
            #pragma unroll
            for (int ntp = 0; ntp < 2; ntp++) {
                const uint32_t addr = stb + PLANE_B
                                      + (bkey + ntp * 16) * (GSA * 2)
                                      + ks * 32 + bkh * 16;
                uint32_t t[4];
                ldm4(t, addr);
                bf[2 * ntp][0] = t[0]; bf[2 * ntp][1] = t[1];
                bf[2 * ntp + 1][0] = t[2]; bf[2 * ntp + 1][1] = t[3];
            }
            #pragma unroll
            for (int mt = 0; mt < 4; mt++)
                #pragma unroll
                for (int nt = 0; nt < 4; nt++)
                    mma16816(acc[mt][nt], af[mt], bf[nt]);
        }
    }

    const int g = lane >> 2, tig = lane & 3;
    const float bscale = sa ? (*sa + *sbv) : 1.0f;
    #pragma unroll
    for (int mt = 0; mt < 4; mt++) {
        const int r0 = row0 + warpM * 64 + mt * 16 + g;
        #pragma unroll
        for (int nt = 0; nt < 4; nt++) {
            const int col = col0 + warpN * 32 + nt * 8 + tig * 2;
            const float b0 = bscale * bias[col];
            const float b1 = bscale * bias[col + 1];
            const float v00 = acc[mt][nt][0] + b0, v01 = acc[mt][nt][1] + b1;
            const float v10 = acc[mt][nt][2] + b0, v11 = acc[mt][nt][3] + b1;
            if (Cf) {
                *(float2*)(Cf + (size_t)r0 * ldc + col)       = make_float2(v00, v01);
                *(float2*)(Cf + (size_t)(r0 + 8) * ldc + col) = make_float2(v10, v11);
            }
            if (Ch) {
                *(__half2*)(Ch + (size_t)r0 * ldc + col) =
                    __halves2half2(__float2half_rn(v00), __float2half_rn(v01));
                *(__half2*)(Ch + (size_t)(r0 + 8) * ldc + col) =
                    __halves2half2(__float2half_rn(v10), __float2half_rn(v11));
            }
        }
    }
}

// ---------------------------------------------------------------------------
// Dual-stream flash attention, fp16 single-plane Q/K/V, both outputs in one
// launch, DOUBLE-BUFFERED KV tiles with one barrier per tile.
// 64 q-rows, 4 warps (128 thr), base-2 softmax with raw ex2.approx.
// blockIdx.x&1 selects output stream; adjacent CTAs share KV tiles in L2.
// smem: [Q][K0][V0][K1][V1]
// ---------------------------------------------------------------------------
#define AST     72                    // fp16 row stride (144B)
#define ROWB    (AST * 2)             // 144
#define ATILE_B (64 * ROWB)           // 9216
#define ATT_SMEM (5 * ATILE_B)        // 46080
#define SC2     0.1803368801f         // 0.125 * log2(e)

__global__ void __launch_bounds__(128)
attn_mma(const __half* __restrict__ qkvx, const __half* __restrict__ qkvy,
         const float* __restrict__ pw11, const float* __restrict__ pw12,
         const float* __restrict__ pw21, const float* __restrict__ pw22,
         __half* __restrict__ cxh, __half* __restrict__ cyh)
{
    extern __shared__ char smem[];
    const uint32_t sb = smem_u32(smem);

    const int st = blockIdx.x & 1;
    const int qt = blockIdx.x >> 1;
    const int h = blockIdx.y, b = blockIdx.z;
    const int tid = threadIdx.x, wid = tid >> 5, lane = tid & 31;
    const int g = lane >> 2, tig = lane & 3;

    const __half* Qh = st ? qkvy : qkvx;
    const __half* const KH[2] = { qkvx + PH, qkvy + PH };
    const __half* const VH[2] = { qkvx + 2 * PH, qkvy + 2 * PH };
    const float ws0 = st ? *pw22 : *pw11;
    const float ws1 = st ? *pw21 : *pw12;
    __half* ctx = st ? cyh : cxh;

    // --- load Q tile via cp.async ---
    #pragma unroll
    for (int j = 0; j < 4; j++) {
        const int cc = j * 128 + tid;
        const int r = cc >> 3, seg = cc & 7;
        const size_t go = (size_t)(b * PS + qt * 64 + r) * LQKV + h * PDH + seg * 8;
        cpasync16(sb + r * ROWB + seg * 16, Qh + go);
    }
    CP_COMMIT();
    CP_WAIT(0);
    __syncthreads();

    // --- Q fragments (registers, reused across phases) ---
    uint32_t qf[4][4];
    {
        const int qrow = wid * 16 + (lane & 15);
        const int khalf = lane >> 4;
        #pragma unroll
        for (int ks = 0; ks < 4; ks++)
            ldm4(qf[ks], sb + qrow * ROWB + ks * 32 + khalf * 16);
    }

    const int bkey = (lane & 7) + ((lane >> 4) << 3);
    const int bkh  = (lane >> 3) & 1;
    const int vkey = (lane & 7) + (((lane >> 3) & 1) << 3);
    const int vdh  = (lane >> 4) << 3;

#define KV_LOAD(Kp, Vp, kt, buf) do {                                         \
    const uint32_t kbase = sb + ATILE_B + (buf) * 2 * ATILE_B;                \
    _Pragma("unroll")                                                         \
    for (int j = 0; j < 4; j++) {                                             \
        const int cc = j * 128 + tid;                                         \
        const int r = cc >> 3, seg = cc & 7;                                  \
        const size_t go = (size_t)(b * PS + (kt) * 64 + r) * LQKV             \
                          + h * PDH + seg * 8;                                \
        const uint32_t so = r * ROWB + seg * 16;                              \
        cpasync16(kbase + so,           Kp + go);                             \
        cpasync16(kbase + ATILE_B + so, Vp + go);                             \
    }                                                                         \
    CP_COMMIT();                                                              \
} while (0)

    float ostash[8][4];

    for (int s = 0; s < 2; s++) {
        const __half* Kh_ = KH[s];
        const __half* Vh_ = VH[s];

        float m[2] = { -1e30f, -1e30f }, l[2] = { 0.0f, 0.0f };
        float oacc[8][4];
        #pragma unroll
        for (int nt = 0; nt < 8; nt++)
            #pragma unroll
            for (int c = 0; c < 4; c++) oacc[nt][c] = 0.0f;

        KV_LOAD(Kh_, Vh_, 0, 0);

        for (int kt = 0; kt < PS / 64; kt++) {
            CP_WAIT(0);          // tile kt resident (this thread's parts)
            __syncthreads();     // all threads' parts visible; compute kt-1 done
            if (kt + 1 < PS / 64)
                KV_LOAD(Kh_, Vh_, kt + 1, (kt + 1) & 1);  // flies during compute

            const uint32_t kh_s = sb + ATILE_B + (kt & 1) * 2 * ATILE_B;
            const uint32_t vh_s = kh_s + ATILE_B;

            // --- scores S = Q @ K^T ---
            float sacc[8][4];
            #pragma unroll
            for (int nt = 0; nt < 8; nt++)
                #pragma unroll
                for (int c = 0; c < 4; c++) sacc[nt][c] = 0.0f;

            #pragma unroll
            for (int ks = 0; ks < 4; ks++) {
                #pragma unroll
                for (int ntp = 0; ntp < 4; ntp++) {
                    const uint32_t addr = kh_s + (ntp * 16 + bkey) * ROWB
                                          + ks * 32 + bkh * 16;
                    uint32_t th[4];
                    ldm4(th, addr);
                    const uint32_t b0h[2] = { th[0], th[1] }, b1h[2] = { th[2], th[3] };
                    mma16816(sacc[2 * ntp],     qf[ks], b0h);
                    mma16816(sacc[2 * ntp + 1], qf[ks], b1h);
                }
            }

            // --- online softmax in base-2 (raw ex2.approx) ---
            #pragma unroll
            for (int nt = 0; nt < 8; nt++)
                #pragma unroll
                for (int c = 0; c < 4; c++) sacc[nt][c] *= SC2;

            #pragma unroll
            for (int half = 0; half < 2; half++) {
                float mx = -1e30f;
                #pragma unroll
                for (int nt = 0; nt < 8; nt++)
                    mx = fmaxf(mx, fmaxf(sacc[nt][2 * half], sacc[nt][2 * half + 1]));
                mx = fmaxf(mx, __shfl_xor_sync(0xffffffffu, mx, 1));
                mx = fmaxf(mx, __shfl_xor_sync(0xffffffffu, mx, 2));
                const float mn = fmaxf(m[half], mx);
                const float corr = ex2(m[half] - mn);
                m[half] = mn;
                float rs = 0.0f;
                #pragma unroll
                for (int nt = 0; nt < 8; nt++) {
                    const float p0 = ex2(sacc[nt][2 * half] - mn);
                    const float p1 = ex2(sacc[nt][2 * half + 1] - mn);
                    sacc[nt][2 * half] = p0;
                    sacc[nt][2 * half + 1] = p1;
                    rs += p0 + p1;
                }
                rs += __shfl_xor_sync(0xffffffffu, rs, 1);
                rs += __shfl_xor_sync(0xffffffffu, rs, 2);
                l[half] = l[half] * corr + rs;
                #pragma unroll
                for (int nt = 0; nt < 8; nt++) {
                    oacc[nt][2 * half]     *= corr;
                    oacc[nt][2 * half + 1] *= corr;
                }
            }

            // --- pack P into fp16 A-fragments ---
            uint32_t ph[8][2];
            #pragma unroll
            for (int nt = 0; nt < 8; nt++) {
                #pragma unroll
                for (int half = 0; half < 2; half++) {
                    ph[nt][half] = packh(__float2half_rn(sacc[nt][2 * half]),
                                         __float2half_rn(sacc[nt][2 * half + 1]));
                }
            }

            // --- O += P @ V ---
            #pragma unroll
            for (int ks = 0; ks < 4; ks++) {
                const uint32_t pa[4] = { ph[2 * ks][0], ph[2 * ks][1],
                                         ph[2 * ks + 1][0], ph[2 * ks + 1][1] };
                #pragma unroll
                for (int dhp = 0; dhp < 4; dhp++) {
                    const uint32_t addr = vh_s + (ks * 16 + vkey) * ROWB
                                          + (dhp * 16 + vdh) * 2;
                    uint32_t th[4];
                    ldm4t(th, addr);
                    const uint32_t b0h[2] = { th[0], th[1] }, b1h[2] = { th[2], th[3] };
                    mma16816(oacc[2 * dhp],     pa, b0h);
                    mma16816(oacc[2 * dhp + 1], pa, b1h);
                }
            }
        }

        if (s == 0) {
            const float i0 = ws0 / l[0], i1 = ws0 / l[1];
            #pragma unroll
            for (int nt = 0; nt < 8; nt++) {
                ostash[nt][0] = oacc[nt][0] * i0;
                ostash[nt][1] = oacc[nt][1] * i0;
                ostash[nt][2] = oacc[nt][2] * i1;
                ostash[nt][3] = oacc[nt][3] * i1;
            }
        } else {
            const float i0 = ws1 / l[0], i1 = ws1 / l[1];
            const int r0 = qt * 64 + wid * 16 + g;
            #pragma unroll
            for (int nt = 0; nt < 8; nt++) {
                const int col = h * PDH + nt * 8 + tig * 2;
                const float v00 = ostash[nt][0] + oacc[nt][0] * i0;
                const float v01 = ostash[nt][1] + oacc[nt][1] * i0;
                const float v10 = ostash[nt][2] + oacc[nt][2] * i1;
                const float v11 = ostash[nt][3] + oacc[nt][3] * i1;
                const size_t o0 = (size_t)(b * PS + r0) * PH + col;
                const size_t o1 = (size_t)(b * PS + r0 + 8) * PH + col;
                *(__half2*)(ctx + o0) = __halves2half2(__float2half_rn(v00),
                                                       __float2half_rn(v01));
                *(__half2*)(ctx + o1) = __halves2half2(__float2half_rn(v10),
                                                       __float2half_rn(v11));
            }
        }
    }
}

// ---------------------------------------------------------------------------
// Launch
// ---------------------------------------------------------------------------
extern "C" void kernel_launch(void* const* d_in, const int* in_sizes, int n_in,
                              void* d_out, int out_size)
{
    const float* hx = (const float*)d_in[0];
    const float* hy = (const float*)d_in[1];
    const float* Wf[8] = { (const float*)d_in[2],  (const float*)d_in[4],
                           (const float*)d_in[6],  (const float*)d_in[8],
                           (const float*)d_in[10], (const float*)d_in[12],
                           (const float*)d_in[14], (const float*)d_in[16] };
    const float* Bf[8] = { (const float*)d_in[3],  (const float*)d_in[5],
                           (const float*)d_in[7],  (const float*)d_in[9],
                           (const float*)d_in[11], (const float*)d_in[13],
                           (const float*)d_in[15], (const float*)d_in[17] };
    // order: 0=q 1=k 2=v 3=o 4=qd 5=kd 6=vd 7=od
    const float* pw11 = (const float*)d_in[18];
    const float* pw12 = (const float*)d_in[19];
    const float* pw21 = (const float*)d_in[20];
    const float* pw22 = (const float*)d_in[21];
    float* out = (float*)d_out;

    __half *xh, *yh, *qkvx, *qkvy, *cxh, *cyh, *w;
    float *bcx, *bcy;
    cudaGetSymbolAddress((void**)&xh,   g_xh);
    cudaGetSymbolAddress((void**)&yh,   g_yh);
    cudaGetSymbolAddress((void**)&qkvx, g_qkvx);
    cudaGetSymbolAddress((void**)&qkvy, g_qkvy);
    cudaGetSymbolAddress((void**)&cxh,  g_cxh);
    cudaGetSymbolAddress((void**)&cyh,  g_cyh);
    cudaGetSymbolAddress((void**)&w,    g_w);
    cudaGetSymbolAddress((void**)&bcx,  g_bcx);
    cudaGetSymbolAddress((void**)&bcy,  g_bcy);

    // conversions + bias concat
    {
        const int n4a = PELEMS / 4, n4w = WN / 4;
        dim3 gi((n4a + 255) / 256, 2);
        cvt_inputs<<<gi, 256>>>(hx, hy, xh, yh);
        dim3 gw((n4w + 255) / 256, 8);
        cvt_weights<<<gw, 256>>>(Wf[0], Wf[1], Wf[2], Wf[3],
                                 Wf[4], Wf[5], Wf[6], Wf[7], w);
        concat_biases<<<dim3(9, 2), 256>>>(Bf[0], Bf[1], Bf[2], bcx,
                                           Bf[4], Bf[5], Bf[6], bcy);
    }

    cudaFuncSetAttribute(mm_gemm, cudaFuncAttributeMaxDynamicSharedMemorySize,
                         GEMM_SMEM);
    cudaFuncSetAttribute(attn_mma, cudaFuncAttributeMaxDynamicSharedMemorySize,
                         ATT_SMEM);

    // fused QKV projections for BOTH streams in one launch (N = 2304)
    {
        const dim3 gq(LQKV / 128, 2 * (PM / 128));    // (18, 128)
        mm_gemm<<<gq, 256, GEMM_SMEM>>>(
            xh, w + 0 * (size_t)WN, bcx, nullptr, nullptr, nullptr, qkvx,
            yh, w + 4 * (size_t)WN, bcy, nullptr, nullptr, nullptr, qkvy,
            PH, LQKV);
    }

    // dual-stream flash attention, both outputs in one launch
    {
        const dim3 ga(2 * (PS / 64), PNH, PB);        // (32, 12, 8)
        attn_mma<<<ga, 128, ATT_SMEM>>>(qkvx, qkvy,
                                        pw11, pw12, pw21, pw22, cxh, cyh);
    }

    // output projections for BOTH streams in one launch
    {
        const dim3 go(PH / 128, 2 * (PM / 128));      // (6, 128)
        mm_gemm<<<go, 256, GEMM_SMEM>>>(
            cxh, w + 3 * (size_t)WN, Bf[3], pw11, pw12, out, nullptr,
            cyh, w + 7 * (size_t)WN, Bf[7], pw21, pw22, out + (size_t)PM * PH, nullptr,
            PH, PH);
    }
}